// round 3
// baseline (speedup 1.0000x reference)
#include <cuda_runtime.h>
#include <math.h>

#define NRES  2048
#define CDIM  256
#define HEADS 8
#define CH    32
#define PQ    8
#define PV    12
#define CZ    32
#define BQ    32
#define BK    128
#define NBLK  64
#define PADK  48
#define PROJW 1440
#define CATW  704
#define NPTS  224   // 64 q-points + 160 kv-points per residue

// ---------------- scratch (static device globals; no allocation) ----------------
__device__ float g_Wgb[CDIM*512];
__device__ float g_bgb[512];
__device__ float g_Wcat[CDIM*PROJW];
__device__ float g_gb[NRES*512];
__device__ float g_snew[NRES*CDIM];
__device__ float g_proj[NRES*PROJW];
__device__ float g_pts[NRES*NPTS*3];
__device__ float g_bbias[NBLK*HEADS*BQ*BK];
__device__ float g_pz[NBLK*BQ*BK*8];
__device__ float g_cat[NRES*CATW];

// ---------------- weight concat kernels ----------------
__global__ void concat_wgb_kernel(const float* __restrict__ Wg, const float* __restrict__ bg,
                                  const float* __restrict__ Wbeta, const float* __restrict__ bbeta) {
    int idx = blockIdx.x*blockDim.x + threadIdx.x;
    if (idx < CDIM*512) {
        int r = idx / 512, c = idx % 512;
        g_Wgb[idx] = (c < 256) ? Wg[r*256 + c] : Wbeta[r*256 + (c-256)];
    }
    if (idx < 512) g_bgb[idx] = (idx < 256) ? bg[idx] : bbeta[idx-256];
}

__global__ void concat_wcat_kernel(const float* __restrict__ Wq, const float* __restrict__ Wk,
                                   const float* __restrict__ Wv, const float* __restrict__ Wqp,
                                   const float* __restrict__ Wkvp) {
    int idx = blockIdx.x*blockDim.x + threadIdx.x;
    if (idx >= CDIM*PROJW) return;
    int r = idx / PROJW, c = idx % PROJW;
    float v;
    if      (c < 256) v = Wq[r*256 + c];
    else if (c < 512) v = Wk[r*256 + (c-256)];
    else if (c < 768) v = Wv[r*256 + (c-512)];
    else if (c < 960) v = Wqp[r*192 + (c-768)];
    else              v = Wkvp[r*480 + (c-960)];
    g_Wcat[idx] = v;
}

// ---------------- generic tiled SGEMM: C = A(MxK) @ B(KxN) [+ bias] ----------------
__global__ void sgemm_kernel(const float* __restrict__ A, const float* __restrict__ B,
                             const float* __restrict__ bias, float* __restrict__ C,
                             int M, int N, int K) {
    __shared__ float As[16][65];   // [kk][m], padded
    __shared__ float Bs[16][64];   // [kk][n]
    const int bm = blockIdx.y * 64;
    const int bn = blockIdx.x * 64;
    const int tid = threadIdx.x;
    const int tx = tid & 15;   // col group (4 cols)
    const int ty = tid >> 4;   // row group (4 rows)
    float acc[4][4];
#pragma unroll
    for (int i = 0; i < 4; i++)
#pragma unroll
        for (int j = 0; j < 4; j++) acc[i][j] = 0.f;

    for (int k0 = 0; k0 < K; k0 += 16) {
#pragma unroll
        for (int t = 0; t < 4; t++) {
            int idx = tid + t*256;       // 0..1023
            int m  = idx >> 4;
            int kk = idx & 15;
            int gm = bm + m, gk = k0 + kk;
            float v = 0.f;
            if (gm < M && gk < K) v = A[gm*K + gk];
            As[kk][m] = v;
        }
#pragma unroll
        for (int t = 0; t < 4; t++) {
            int idx = tid + t*256;
            int kk = idx >> 6;
            int n  = idx & 63;
            int gn = bn + n, gk = k0 + kk;
            float v = 0.f;
            if (gk < K && gn < N) v = B[gk*N + gn];
            Bs[kk][n] = v;
        }
        __syncthreads();
#pragma unroll
        for (int kk = 0; kk < 16; kk++) {
            float a0 = As[kk][ty*4+0], a1 = As[kk][ty*4+1];
            float a2 = As[kk][ty*4+2], a3 = As[kk][ty*4+3];
            float b0 = Bs[kk][tx*4+0], b1 = Bs[kk][tx*4+1];
            float b2 = Bs[kk][tx*4+2], b3 = Bs[kk][tx*4+3];
            acc[0][0] += a0*b0; acc[0][1] += a0*b1; acc[0][2] += a0*b2; acc[0][3] += a0*b3;
            acc[1][0] += a1*b0; acc[1][1] += a1*b1; acc[1][2] += a1*b2; acc[1][3] += a1*b3;
            acc[2][0] += a2*b0; acc[2][1] += a2*b1; acc[2][2] += a2*b2; acc[2][3] += a2*b3;
            acc[3][0] += a3*b0; acc[3][1] += a3*b1; acc[3][2] += a3*b2; acc[3][3] += a3*b3;
        }
        __syncthreads();
    }
#pragma unroll
    for (int i = 0; i < 4; i++) {
        int gm = bm + ty*4 + i;
        if (gm >= M) continue;
#pragma unroll
        for (int j = 0; j < 4; j++) {
            int gn = bn + tx*4 + j;
            if (gn >= N) continue;
            float v = acc[i][j];
            if (bias) v += bias[gn];
            C[gm*N + gn] = v;
        }
    }
}

// ---------------- s layernorm + conditioning modulate ----------------
__global__ void ln_s_kernel(const float* __restrict__ s) {
    int n = blockIdx.x;
    int c = threadIdx.x;     // 256 threads
    float x = s[n*CDIM + c];
    float sum = x, sq = x*x;
#pragma unroll
    for (int o = 16; o > 0; o >>= 1) {
        sum += __shfl_xor_sync(0xffffffffu, sum, o);
        sq  += __shfl_xor_sync(0xffffffffu, sq,  o);
    }
    __shared__ float ssum[8], ssq[8];
    int w = c >> 5, l = c & 31;
    if (l == 0) { ssum[w] = sum; ssq[w] = sq; }
    __syncthreads();
    if (w == 0) {
        float a = (l < 8) ? ssum[l] : 0.f;
        float b = (l < 8) ? ssq[l]  : 0.f;
#pragma unroll
        for (int o = 4; o > 0; o >>= 1) {
            a += __shfl_xor_sync(0xffffffffu, a, o);
            b += __shfl_xor_sync(0xffffffffu, b, o);
        }
        if (l == 0) { ssum[0] = a; ssq[0] = b; }
    }
    __syncthreads();
    float mean = ssum[0] * (1.f/CDIM);
    float var  = ssq[0]  * (1.f/CDIM) - mean*mean;
    float rstd = rsqrtf(var + 1e-5f);
    g_snew[n*CDIM + c] = (x - mean)*rstd * g_gb[n*512 + c] + g_gb[n*512 + 256 + c];
}

// ---------------- per-residue point frame transform: pt = R*raw + t ----------------
__global__ void pts_kernel(const float* __restrict__ trans, const float* __restrict__ rots) {
    int n = blockIdx.x;
    int p = threadIdx.x;     // 224 threads == NPTS
    __shared__ float R[9], t[3];
    if (threadIdx.x < 9) R[threadIdx.x] = rots[n*9 + threadIdx.x];
    if (threadIdx.x < 3) t[threadIdx.x] = trans[n*3 + threadIdx.x];
    __syncthreads();
    const float* src = g_proj + n*PROJW + 768 + p*3;  // 768..1440 = 224 points * 3
    float x = src[0], y = src[1], z = src[2];
    float ox = R[0]*x + R[1]*y + R[2]*z + t[0];
    float oy = R[3]*x + R[4]*y + R[5]*z + t[1];
    float oz = R[6]*x + R[7]*y + R[8]*z + t[2];
    float* dst = g_pts + (n*NPTS + p)*3;
    dst[0] = ox; dst[1] = oy; dst[2] = oz;
}

// ---------------- z: layernorm*g+b, then b=z@Wb (scaled sqrt(1/3)) and pz=z@Wdz ----------------
__global__ void zln_kernel(const float* __restrict__ z, const float* __restrict__ Wb,
                           const float* __restrict__ Wdz, const float* __restrict__ gz,
                           const float* __restrict__ bz) {
    __shared__ float sWb[CZ*8], sWdz[CZ*8], sgz[CZ], sbz[CZ];
    int tid = threadIdx.x;   // 256
    sWb[tid]  = Wb[tid];
    sWdz[tid] = Wdz[tid];
    if (tid < CZ) { sgz[tid] = gz[tid]; sbz[tid] = bz[tid]; }
    __syncthreads();

    int pair = blockIdx.x*256 + tid;          // 0..NBLK*BQ*BK-1
    const float* zr = z + (size_t)pair * CZ;
    float v[CZ];
    float sum = 0.f, sq = 0.f;
#pragma unroll
    for (int c = 0; c < CZ; c++) { float x = zr[c]; v[c] = x; sum += x; sq += x*x; }
    float mean = sum * (1.f/CZ);
    float var  = sq  * (1.f/CZ) - mean*mean;
    float rstd = rsqrtf(var + 1e-5f);
#pragma unroll
    for (int c = 0; c < CZ; c++) v[c] = (v[c]-mean)*rstd*sgz[c] + sbz[c];

    float ob[8], op[8];
#pragma unroll
    for (int h = 0; h < 8; h++) { ob[h] = 0.f; op[h] = 0.f; }
#pragma unroll
    for (int c = 0; c < CZ; c++) {
        float x = v[c];
#pragma unroll
        for (int h = 0; h < 8; h++) {
            ob[h] += x * sWb[c*8 + h];
            op[h] += x * sWdz[c*8 + h];
        }
    }
    int k  = pair & 127;
    int q  = (pair >> 7) & 31;
    int nb = pair >> 12;
#pragma unroll
    for (int h = 0; h < 8; h++)
        g_bbias[(((nb*HEADS + h)*BQ + q)*BK) + k] = ob[h] * 0.5773502691896258f; // sqrt(1/3)
    float* pzd = g_pz + (size_t)pair * 8;
#pragma unroll
    for (int c = 0; c < 8; c++) pzd[c] = op[c];
}

// ---------------- attention: one block per (nb, h) ----------------
#define ATTN_SMEM_FLOATS (32*33 + 128*33 + 128*33 + 32*25 + 128*25 + 128*37 + 32*129 + 32*37 + 96 + 288 + 128 + 32)

__global__ void attn_kernel(const float* __restrict__ trans, const float* __restrict__ rots,
                            const float* __restrict__ smaskp, const float* __restrict__ headw) {
    extern __shared__ float sm[];
    float* qs   = sm;                 // [32][33]
    float* ks   = qs   + 32*33;       // [128][33]
    float* vs   = ks   + 128*33;      // [128][33]
    float* qp   = vs   + 128*33;      // [32][25]
    float* kp   = qp   + 32*25;       // [128][25]
    float* vp   = kp   + 128*25;      // [128][37]
    float* am   = vp   + 128*37;      // [32][129] attention scores/probs
    float* optg = am   + 32*129;      // [32][37]
    float* qt   = optg + 32*37;       // [32][3]
    float* qR   = qt   + 96;          // [32][9]
    float* mk   = qR   + 288;         // [128]
    float* smq  = mk   + 128;         // [32]

    const int nb  = blockIdx.x;
    const int h   = blockIdx.y;
    const int tid = threadIdx.x;      // 128

    for (int i = tid; i < 32*32; i += 128) {
        int q = i >> 5, c = i & 31;
        qs[q*33 + c] = g_proj[(nb*BQ + q)*PROJW + h*CH + c];
    }
    for (int i = tid; i < 128*32; i += 128) {
        int k = i >> 5, c = i & 31;
        int kidx = nb*BQ + k - PADK;
        bool valid = (kidx >= 0 && kidx < NRES);
        ks[k*33 + c] = valid ? g_proj[kidx*PROJW + 256 + h*CH + c] : 0.f;
        vs[k*33 + c] = valid ? g_proj[kidx*PROJW + 512 + h*CH + c] : 0.f;
    }
    for (int i = tid; i < 32*24; i += 128) {
        int q = i / 24, j = i % 24;
        qp[q*25 + j] = g_pts[((nb*BQ + q)*NPTS + h*PQ + j/3)*3 + (j%3)];
    }
    for (int i = tid; i < 128*24; i += 128) {
        int k = i / 24, j = i % 24;
        int kidx = nb*BQ + k - PADK;
        bool valid = (kidx >= 0 && kidx < NRES);
        kp[k*25 + j] = valid ? g_pts[(kidx*NPTS + 64 + h*20 + j/3)*3 + (j%3)] : 0.f;
    }
    for (int i = tid; i < 128*36; i += 128) {
        int k = i / 36, j = i % 36;
        int kidx = nb*BQ + k - PADK;
        bool valid = (kidx >= 0 && kidx < NRES);
        vp[k*37 + j] = valid ? g_pts[(kidx*NPTS + 64 + h*20 + 8 + j/3)*3 + (j%3)] : 0.f;
    }
    for (int i = tid; i < 32*128; i += 128) {
        int q = i >> 7, k = i & 127;
        am[q*129 + k] = g_bbias[((nb*HEADS + h)*BQ + q)*BK + k];
    }
    for (int i = tid; i < 96;  i += 128) qt[i] = trans[(nb*BQ + i/3)*3 + (i%3)];
    for (int i = tid; i < 288; i += 128) qR[i] = rots[(nb*BQ + i/9)*9 + (i%9)];
    {
        int kidx = nb*BQ + tid - PADK;
        mk[tid] = (kidx >= 0 && kidx < NRES) ? smaskp[kidx] : 0.f;
        if (tid < 32) smq[tid] = smaskp[nb*BQ + tid];
    }
    __syncthreads();

    float hww = headw[h];
    hww = ((hww > 20.f) ? hww : log1pf(expf(hww))) * 0.09622504486493763f; // softplus * sqrt(1/108)

    // register-cache this thread's key (k = tid)
    float kreg[32], kpr[24];
#pragma unroll
    for (int c = 0; c < 32; c++) kreg[c] = ks[tid*33 + c];
#pragma unroll
    for (int j = 0; j < 24; j++) kpr[j] = kp[tid*25 + j];
    const float maskk = mk[tid];

    for (int q = 0; q < 32; q++) {
        float dot = 0.f;
#pragma unroll
        for (int c = 0; c < 32; c++) dot += qs[q*33 + c] * kreg[c];
        float d2 = 0.f;
#pragma unroll
        for (int p = 0; p < 8; p++) {
            float dx = qp[q*25 + p*3 + 0] - kpr[p*3 + 0];
            float dy = qp[q*25 + p*3 + 1] - kpr[p*3 + 1];
            float dz = qp[q*25 + p*3 + 2] - kpr[p*3 + 2];
            d2 += dx*dx + dy*dy + dz*dz;
        }
        float sc = dot * 0.10206207261596577f      // sqrt(1/96)
                 + am[q*129 + tid]                 // sqrt(1/3)*b (pre-scaled)
                 - 0.5f * hww * d2
                 + 1e8f * (smq[q]*maskk - 1.f);
        am[q*129 + tid] = sc;
    }
    __syncthreads();

    // softmax over k per (q): 4 threads per row
    {
        int q = tid >> 2, sub = tid & 3;
        float mx = -1e30f;
#pragma unroll
        for (int j = 0; j < 32; j++) mx = fmaxf(mx, am[q*129 + sub + 4*j]);
        mx = fmaxf(mx, __shfl_xor_sync(0xffffffffu, mx, 1));
        mx = fmaxf(mx, __shfl_xor_sync(0xffffffffu, mx, 2));
        float ssum = 0.f;
#pragma unroll
        for (int j = 0; j < 32; j++) {
            float e = expf(am[q*129 + sub + 4*j] - mx);
            am[q*129 + sub + 4*j] = e;
            ssum += e;
        }
        ssum += __shfl_xor_sync(0xffffffffu, ssum, 1);
        ssum += __shfl_xor_sync(0xffffffffu, ssum, 2);
        float inv = 1.f / ssum;
#pragma unroll
        for (int j = 0; j < 32; j++) am[q*129 + sub + 4*j] *= inv;
    }
    __syncthreads();

    // o = a @ v  -> cat[:, h*32 + c]
    {
        int c = tid & 31, qg = tid >> 5;
        for (int qq = 0; qq < 8; qq++) {
            int q = qg + 4*qq;
            float acc = 0.f;
            for (int k = 0; k < 128; k++) acc += am[q*129 + k] * vs[k*33 + c];
            g_cat[(nb*BQ + q)*CATW + h*CH + c] = acc;
        }
    }
    // o_pt (global frame) = a @ v_pts
    for (int i = tid; i < 32*36; i += 128) {
        int q = i / 36, col = i % 36;
        float acc = 0.f;
        for (int k = 0; k < 128; k++) acc += am[q*129 + k] * vp[k*37 + col];
        optg[q*37 + col] = acc;
    }
    // o_pair = a @ pair_z
    for (int i = tid; i < 32*8; i += 128) {
        int q = i >> 3, c8 = i & 7;
        const float* pzr = g_pz + ((size_t)(nb*BQ + q)*BK)*8 + c8;
        float acc = 0.f;
        for (int k = 0; k < 128; k++) acc += am[q*129 + k] * pzr[k*8];
        g_cat[(nb*BQ + q)*CATW + 640 + h*8 + c8] = acc;
    }
    __syncthreads();

    // invert frames: local = R^T (global - t); norms
    for (int i = tid; i < 32*12; i += 128) {
        int q = i / 12, v = i % 12;
        float gx = optg[q*37 + v*3 + 0] - qt[q*3 + 0];
        float gy = optg[q*37 + v*3 + 1] - qt[q*3 + 1];
        float gz = optg[q*37 + v*3 + 2] - qt[q*3 + 2];
        const float* R = qR + q*9;
        float lx = R[0]*gx + R[3]*gy + R[6]*gz;
        float ly = R[1]*gx + R[4]*gy + R[7]*gz;
        float lz = R[2]*gx + R[5]*gy + R[8]*gz;
        int n = nb*BQ + q;
        g_cat[n*CATW + 256 + h*36 + v*3 + 0] = lx;
        g_cat[n*CATW + 256 + h*36 + v*3 + 1] = ly;
        g_cat[n*CATW + 256 + h*36 + v*3 + 2] = lz;
        g_cat[n*CATW + 544 + h*12 + v] = sqrtf(lx*lx + ly*ly + lz*lz + 1e-8f);
    }
}

// ---------------- launch ----------------
static float* symaddr(const void* sym) {
    void* p = nullptr;
    cudaGetSymbolAddress(&p, sym);
    return (float*)p;
}

extern "C" void kernel_launch(void* const* d_in, const int* in_sizes, int n_in,
                              void* d_out, int out_size) {
    const float* s      = (const float*)d_in[0];
    const float* cond   = (const float*)d_in[1];
    const float* z      = (const float*)d_in[2];
    const float* trans  = (const float*)d_in[3];
    const float* rots   = (const float*)d_in[4];
    const float* smask  = (const float*)d_in[5];
    const float* Wq     = (const float*)d_in[6];
    const float* Wk     = (const float*)d_in[7];
    const float* Wv     = (const float*)d_in[8];
    const float* Wqp    = (const float*)d_in[9];
    const float* Wkvp   = (const float*)d_in[10];
    const float* Wb     = (const float*)d_in[11];
    const float* Wdz    = (const float*)d_in[12];
    const float* headw  = (const float*)d_in[13];
    const float* Wout   = (const float*)d_in[14];
    const float* Wg     = (const float*)d_in[15];
    const float* bg     = (const float*)d_in[16];
    const float* Wbeta  = (const float*)d_in[17];
    const float* bbeta  = (const float*)d_in[18];
    const float* gz     = (const float*)d_in[19];
    const float* bz     = (const float*)d_in[20];
    float* out = (float*)d_out;

    float* p_Wgb  = symaddr(g_Wgb);
    float* p_bgb  = symaddr(g_bgb);
    float* p_Wcat = symaddr(g_Wcat);
    float* p_gb   = symaddr(g_gb);
    float* p_snew = symaddr(g_snew);
    float* p_proj = symaddr(g_proj);
    float* p_cat  = symaddr(g_cat);

    const size_t attn_smem = ATTN_SMEM_FLOATS * sizeof(float);
    cudaFuncSetAttribute(attn_kernel, cudaFuncAttributeMaxDynamicSharedMemorySize, (int)attn_smem);

    // 1) weight concats
    concat_wgb_kernel<<<(CDIM*512 + 255)/256, 256>>>(Wg, bg, Wbeta, bbeta);
    concat_wcat_kernel<<<(CDIM*PROJW + 255)/256, 256>>>(Wq, Wk, Wv, Wqp, Wkvp);

    // 2) gb = cond @ [Wg|Wbeta] + [bg|bbeta]
    sgemm_kernel<<<dim3(512/64, NRES/64), 256>>>(cond, p_Wgb, p_bgb, p_gb, NRES, 512, CDIM);

    // 3) s_new = ln(s)*gamma + beta
    ln_s_kernel<<<NRES, CDIM>>>(s);

    // 4) proj = s_new @ Wcat
    sgemm_kernel<<<dim3((PROJW + 63)/64, NRES/64), 256>>>(p_snew, p_Wcat, nullptr, p_proj, NRES, PROJW, CDIM);

    // 5) frame-transform points
    pts_kernel<<<NRES, NPTS>>>(trans, rots);

    // 6) z layernorm + b + pair_z
    zln_kernel<<<(NBLK*BQ*BK)/256, 256>>>(z, Wb, Wdz, gz, bz);

    // 7) attention per (block, head)
    attn_kernel<<<dim3(NBLK, HEADS), 128, attn_smem>>>(trans, rots, smask, headw);

    // 8) out = cat @ Wout
    sgemm_kernel<<<dim3(CDIM/64, NRES/64), 256>>>(p_cat, Wout, nullptr, out, NRES, CDIM, CATW);
}